// round 14
// baseline (speedup 1.0000x reference)
#include <cuda_runtime.h>
#include <math.h>

#define NPTS   4096
#define NBATCH 16
#define NSAMP  1024
#define NK     32
#define NROWS  (NBATCH*NSAMP*NK)      /* 524288 */
#define NSAMPT (NBATCH*NSAMP)         /* 16384  */
#define OUT_OFF (NBATCH*NSAMP*3)      /* 49152  */

// ---------------- device scratch (no allocations allowed) ----------------
__device__ float  g_centroids[NBATCH*NSAMP*3];
__device__ float  g_x0[(size_t)NROWS*68];
__device__ float  g_y0[(size_t)NROWS*64];
__device__ float  g_y1[(size_t)NROWS*64];
__device__ float  g_ymax[(size_t)NSAMPT*128];
__device__ float  g_ymin[(size_t)NSAMPT*128];
__device__ double g_sums[512];
__device__ float  g_scale[256];
__device__ float  g_shift[256];

__global__ void zero_stats_kernel() {
    int t = threadIdx.x;
    if (t < 512) g_sums[t] = 0.0;
}

// no-op: keeps the fixed-position ncu capture on build_kernel
__global__ void probe_kernel() {}

// ---------------- packed f32x2 helpers (exact RN f32 math) ---------------
__device__ __forceinline__ unsigned long long pk_dup(float x) {
    unsigned long long r; unsigned u = __float_as_uint(x);
    asm("mov.b64 %0, {%1, %1};" : "=l"(r) : "r"(u));
    return r;
}
__device__ __forceinline__ void fma2(unsigned long long& d, unsigned long long a,
                                     unsigned long long b) {
    asm("fma.rn.f32x2 %0, %1, %2, %0;" : "+l"(d) : "l"(a), "l"(b));
}
__device__ __forceinline__ void unpk(unsigned long long v, float& lo, float& hi) {
    unsigned a, b;
    asm("mov.b64 {%0, %1}, %2;" : "=r"(a), "=r"(b) : "l"(v));
    lo = __uint_as_float(a); hi = __uint_as_float(b);
}

// ============================ FPS (REDUX version, banked win) ==============
__global__ __launch_bounds__(1024) void fps_kernel(const float* __restrict__ data,
                                                   const int* __restrict__ initf,
                                                   float* __restrict__ out) {
    extern __shared__ float fsm[];
    float* s_px = fsm;
    float* s_py = fsm + NPTS;
    float* s_pz = fsm + 2*NPTS;
    unsigned* s_rd = (unsigned*)(fsm + 3*NPTS);   // 64 (double-buffered)
    unsigned* s_ri = s_rd + 64;

    const int b = blockIdx.x, tid = threadIdx.x;
    const int lane = tid & 31, wid = tid >> 5;
    const float* db = data + (size_t)b * NPTS * 3;

    float px[4], py[4], pz[4], dist[4];
#pragma unroll
    for (int i = 0; i < 4; i++) {
        int n = tid + i * 1024;
        float x = db[n*3+0], y = db[n*3+1], z = db[n*3+2];
        px[i] = x; py[i] = y; pz[i] = z;
        s_px[n] = x; s_py[n] = y; s_pz[n] = z;
        dist[i] = 1e10f;
    }
    int far = __ldg(initf + b);
    __syncthreads();

    for (int s = 0; s < NSAMP; s++) {
        float cx = s_px[far], cy = s_py[far], cz = s_pz[far];
        if (tid == 0) {
            int o = (b*NSAMP + s) * 3;
            out[o] = cx; out[o+1] = cy; out[o+2] = cz;
            g_centroids[o] = cx; g_centroids[o+1] = cy; g_centroids[o+2] = cz;
        }
        unsigned long long best = 0ull;
#pragma unroll
        for (int i = 0; i < 4; i++) {
            float dx = px[i]-cx, dy = py[i]-cy, dz = pz[i]-cz;
            float d = dx*dx + dy*dy + dz*dz;
            dist[i] = fminf(dist[i], d);
            unsigned long long key =
                ((unsigned long long)__float_as_uint(dist[i]) << 32) |
                (unsigned)(4095 - (tid + i*1024));
            best = best > key ? best : key;
        }
        unsigned d32 = (unsigned)(best >> 32);
        unsigned i32 = (unsigned)best;
        unsigned wd = __reduce_max_sync(0xffffffffu, d32);
        unsigned ci = (d32 == wd) ? i32 : 0u;
        unsigned wi = __reduce_max_sync(0xffffffffu, ci);
        int par = (s & 1) * 32;
        if (lane == 0) { s_rd[par + wid] = wd; s_ri[par + wid] = wi; }
        __syncthreads();
        unsigned dv = s_rd[par + lane], iv = s_ri[par + lane];
        unsigned gd = __reduce_max_sync(0xffffffffu, dv);
        unsigned c2 = (dv == gd) ? iv : 0u;
        unsigned gi = __reduce_max_sync(0xffffffffu, c2);
        far = 4095 - (int)gi;
    }
}

// ==================== stage 2+3: top64 -> top32 -> x0 rows ================
struct Stage3 {
    float px[64], py[64], pz[64];
    unsigned long long sk[64];
    float snx[32], sny[32], snz[32], zw[32];
    int   tk[32];
};

__device__ __forceinline__ unsigned ord_f32(float v) {
    unsigned u = __float_as_uint(v);
    return (u & 0x80000000u) ? ~u : (u | 0x80000000u);
}

// Bit-exact replication of the reference square-dist (verified passing):
__device__ __forceinline__ float sqdist_ref(float cx, float cy, float cz, float an2,
                                            float x, float y, float z) {
    float e   = __fmaf_rn(cz, z, __fmaf_rn(cy, y, __fmul_rn(cx, x)));
    float bn2 = __fadd_rn(__fadd_rn(__fmul_rn(x, x), __fmul_rn(y, y)), __fmul_rn(z, z));
    return __fadd_rn(__fadd_rn(__fmul_rn(-2.f, e), an2), bn2);
}

// 512 threads, 33.8KB smem, 2048 bins. Both bitonic sorts now run on warp 0
// only with __syncwarp (same compare-exchange network -> bit-identical), which
// removes ~49 CTA-wide barriers and their 16-warp issue overhead.
__global__ __launch_bounds__(512) void build_kernel(const float* __restrict__ data,
                                                    const float* __restrict__ feat) {
    extern __shared__ char bsm[];
    unsigned*           s_u    = (unsigned*)bsm;                      // 4096*4 = 16384
    unsigned int*       s_hist = (unsigned int*)(bsm + 16384);        // 2048*4 = 8192
    unsigned long long* s_cand = (unsigned long long*)(bsm + 24576);  // 1024*8 = 8192
    int*                s_tot  = (int*)(bsm + 32768);                 // 256*4  = 1024
    int*                s_ctl  = (int*)(bsm + 33792);                 // [0]=T [1]=m

    const int tid = threadIdx.x;
    const int b = blockIdx.x >> 10, s = blockIdx.x & 1023;
    const float* db = data + (size_t)b * NPTS * 3;
    const int co = (b*NSAMP + s) * 3;
    const float cx = g_centroids[co], cy = g_centroids[co+1], cz = g_centroids[co+2];
    const float an2 = __fadd_rn(__fadd_rn(__fmul_rn(cx, cx), __fmul_rn(cy, cy)),
                                __fmul_rn(cz, cz));

    {
        uint4* hz = (uint4*)s_hist;
        for (int i = tid; i < 512; i += 512) hz[i] = make_uint4(0u, 0u, 0u, 0u);
    }
    if (tid == 0) s_ctl[1] = 0;
    __syncthreads();

    // pass 1: compute 32-bit ordered keys once, cache, histogram top 11 bits
    for (int i = 0; i < 8; i++) {
        int n = tid + i * 512;
        float x = db[n*3], y = db[n*3+1], z = db[n*3+2];
        float v = sqdist_ref(cx, cy, cz, an2, x, y, z);
        unsigned u = ord_f32(v);
        s_u[n] = u;
        atomicAdd(&s_hist[u >> 21], 1u);
    }
    __syncthreads();

    // chunk totals (8 bins per thread, 256 chunks), then single-warp suffix scan
    if (tid < 256) {
        unsigned tot = 0;
        for (int j = 0; j < 8; j++) tot += s_hist[tid*8 + j];
        s_tot[tid] = (int)tot;
    }
    __syncthreads();
    if (tid < 32) {
        int base = tid * 8;
        int t[8]; int S = 0;
#pragma unroll
        for (int j = 0; j < 8; j++) { t[j] = s_tot[base + j]; S += t[j]; }
        int suf = S;   // inclusive suffix over lanes
#pragma unroll
        for (int off = 1; off < 32; off <<= 1) {
            int v = __shfl_down_sync(0xffffffffu, suf, off);
            if (tid + off < 32) suf += v;
        }
        int run = suf - S;   // sum of chunks above this lane's range
#pragma unroll
        for (int j = 7; j >= 0; j--) {
            s_tot[base + j] = run;   // cum[c] = totals of chunks > c
            run += t[j];
        }
    }
    __syncthreads();
    if (tid < 256) {
        unsigned cum = (unsigned)s_tot[tid];
        for (int j = 7; j >= 0; j--) {
            unsigned h = s_hist[tid*8 + j];
            if (cum < 64u && cum + h >= 64u) s_ctl[0] = tid*8 + j;   // unique crossing
            cum += h;
        }
    }
    __syncthreads();
    const unsigned T = (unsigned)s_ctl[0];

    // pass 2: pure smem scan of cached keys, push candidates with bin >= T
    for (int i = 0; i < 8; i++) {
        int n = tid + i * 512;
        unsigned u = s_u[n];
        if ((u >> 21) >= T) {
            int slot = atomicAdd(&s_ctl[1], 1);
            if (slot < 1024)
                s_cand[slot] = ((unsigned long long)u << 32) | (unsigned)(4095 - n);
        }
    }
    __syncthreads();
    int M = s_ctl[1]; if (M > 1024) M = 1024;
    int P = 64; while (P < M) P <<= 1;
    for (int i = M + tid; i < P; i += 512) s_cand[i] = 0ull;
    __syncthreads();

    // bitonic sort descending — warp 0 only, same network, bit-identical
    if (tid < 32) {
        for (int k = 2; k <= P; k <<= 1)
            for (int j = k >> 1; j > 0; j >>= 1) {
                for (int i = tid; i < P; i += 32) {
                    int ix = i ^ j;
                    if (ix > i) {
                        unsigned long long a = s_cand[i], c = s_cand[ix];
                        if (((i & k) == 0) ? (a < c) : (a > c)) { s_cand[i] = c; s_cand[ix] = a; }
                    }
                }
                __syncwarp();
            }
    }
    __syncthreads();

    Stage3* st = (Stage3*)s_hist;   // alias dead histogram (8KB >= 1.9KB)
    if (tid < 64) {
        int id = 4095 - (int)(unsigned)(s_cand[tid] & 0xFFFFFFFFull);
        st->px[tid] = db[id*3]; st->py[tid] = db[id*3+1]; st->pz[tid] = db[id*3+2];
    }
    __syncthreads();
    if (tid < 64) {
        float sc = fabsf(st->pz[tid] - st->pz[(tid + 63) & 63]);   // roll(+1)
        st->sk[tid] = ((unsigned long long)__float_as_uint(sc) << 32) | (unsigned)(63 - tid);
    }
    __syncthreads();

    // 64-element score sort — warp 0 only, same network
    if (tid < 32) {
        for (int k = 2; k <= 64; k <<= 1)
            for (int j = k >> 1; j > 0; j >>= 1) {
                for (int i = tid; i < 64; i += 32) {
                    int ix = i ^ j;
                    if (ix > i) {
                        unsigned long long a = st->sk[i], c = st->sk[ix];
                        if (((i & k) == 0) ? (a < c) : (a > c)) { st->sk[i] = c; st->sk[ix] = a; }
                    }
                }
                __syncwarp();
            }
    }
    __syncthreads();

    if (tid < 32) {
        int j = 63 - (int)(unsigned)(st->sk[tid] & 63ull);   // tki
        float sx = st->px[j] - cx, sy = st->py[j] - cy, sz = st->pz[j] - cz;
        float w = fabsf(st->pz[j] - cz);
        float m = w;
#pragma unroll
        for (int off = 16; off; off >>= 1) m = fmaxf(m, __shfl_xor_sync(0xffffffffu, m, off));
        float e = expf(w - m);
        float su = e;
#pragma unroll
        for (int off = 16; off; off >>= 1) su += __shfl_xor_sync(0xffffffffu, su, off);
        st->snx[tid] = sx; st->sny[tid] = sy; st->snz[tid] = sz;
        st->zw[tid] = e / su;
        st->tk[tid] = j;
    }
    __syncthreads();

    size_t R0 = (size_t)(b*NSAMP + s) * NK;
    for (int e = tid; e < NK * 68; e += 512) {
        int k = e / 68, c = e - k * 68;
        float val;
        if (c < 3)        val = (c == 0 ? st->snx[k] : (c == 1 ? st->sny[k] : st->snz[k])) * st->zw[k];
        else if (c < 67)  val = feat[((size_t)b*NPTS + st->tk[k]) * 64 + (c - 3)] * st->zw[k];
        else              val = 0.f;
        g_x0[(R0 + k) * 68 + c] = val;
    }
}

// ==================== GEMM layers 0/1 (round-5 verbatim, 219us) ===========
template<int LAYER>
__global__ __launch_bounds__(256) void gemm01_kernel(const float* __restrict__ W,
                                                     const float* __restrict__ bias) {
    constexpr int KIN   = (LAYER == 0) ? 68 : 64;
    constexpr int KREAL = (LAYER == 0) ? 67 : 64;
    constexpr int OUT   = 64;
    constexpr int RPB   = 128;
    constexpr int XS    = RPB + 4;

    extern __shared__ float sm[];
    float* s_x = sm;                 // [KIN][XS]
    float* s_w = sm + KIN * XS;      // [KIN][OUT]

    const float* X = (LAYER == 0) ? g_x0 : g_y0;
    float*       Y = (LAYER == 0) ? g_y0 : g_y1;
    double* sums = g_sums + ((LAYER == 0) ? 0 : 128);

    const int tid = threadIdx.x;
    const int cg = tid >> 5, rg = tid & 31;
    const size_t row0 = (size_t)blockIdx.x * RPB;

    for (int i = tid; i < KIN * OUT; i += 256) {
        int k = i / OUT, c = i - k * OUT;
        s_w[k * OUT + c] = (k < KREAL) ? W[c * KREAL + k] : 0.f;
    }
    for (int i = tid; i < RPB * KIN; i += 256) {
        int r = i / KIN, k = i - r * KIN;
        float v = X[(row0 + r) * KIN + k];
        if (LAYER > 0)
            v = fmaxf(fmaf(v, __ldg(&g_scale[k]), __ldg(&g_shift[k])), 0.f);
        s_x[k * XS + r] = v;
    }
    __syncthreads();

    unsigned long long acc[4][4];
#pragma unroll
    for (int i = 0; i < 4; i++)
#pragma unroll
        for (int j = 0; j < 4; j++) acc[i][j] = 0ull;

    const unsigned long long* s_w2 = (const unsigned long long*)s_w;
#pragma unroll 4
    for (int k = 0; k < KIN; k++) {
        float4 xq = *(const float4*)(s_x + k * XS + 4 * rg);
        unsigned long long a0 = pk_dup(xq.x), a1 = pk_dup(xq.y),
                           a2 = pk_dup(xq.z), a3 = pk_dup(xq.w);
        ulonglong2 b01 = *(const ulonglong2*)(s_w2 + ((k * OUT + cg * 8) >> 1));
        ulonglong2 b23 = *(const ulonglong2*)(s_w2 + ((k * OUT + cg * 8) >> 1) + 2);
        fma2(acc[0][0], a0, b01.x); fma2(acc[0][1], a0, b01.y);
        fma2(acc[0][2], a0, b23.x); fma2(acc[0][3], a0, b23.y);
        fma2(acc[1][0], a1, b01.x); fma2(acc[1][1], a1, b01.y);
        fma2(acc[1][2], a1, b23.x); fma2(acc[1][3], a1, b23.y);
        fma2(acc[2][0], a2, b01.x); fma2(acc[2][1], a2, b01.y);
        fma2(acc[2][2], a2, b23.x); fma2(acc[2][3], a2, b23.y);
        fma2(acc[3][0], a3, b01.x); fma2(acc[3][1], a3, b01.y);
        fma2(acc[3][2], a3, b23.x); fma2(acc[3][3], a3, b23.y);
    }

    float bl[8];
#pragma unroll
    for (int j = 0; j < 8; j++) bl[j] = bias[cg * 8 + j];
    float psum[8], psq[8];
#pragma unroll
    for (int j = 0; j < 8; j++) { psum[j] = 0.f; psq[j] = 0.f; }

#pragma unroll
    for (int r = 0; r < 4; r++) {
        float yv[8];
#pragma unroll
        for (int jp = 0; jp < 4; jp++) unpk(acc[r][jp], yv[2*jp], yv[2*jp+1]);
#pragma unroll
        for (int j = 0; j < 8; j++) {
            yv[j] = yv[j] + bl[j];
            psum[j] += yv[j];
            psq[j]  = fmaf(yv[j], yv[j], psq[j]);
        }
        size_t row = row0 + 4 * rg + r;
        float4* dst = (float4*)&Y[row * OUT + cg * 8];
        dst[0] = make_float4(yv[0], yv[1], yv[2], yv[3]);
        dst[1] = make_float4(yv[4], yv[5], yv[6], yv[7]);
    }
#pragma unroll
    for (int j = 0; j < 8; j++) {
#pragma unroll
        for (int off = 16; off; off >>= 1) {
            psum[j] += __shfl_down_sync(0xffffffffu, psum[j], off);
            psq[j]  += __shfl_down_sync(0xffffffffu, psq[j],  off);
        }
    }
    if ((tid & 31) == 0) {
#pragma unroll
        for (int j = 0; j < 8; j++) {
            atomicAdd(&sums[cg * 8 + j],       (double)psum[j]);
            atomicAdd(&sums[OUT + cg * 8 + j], (double)psq[j]);
        }
    }
}

// ==== GEMM layer 2: col-split (grid.y=2), gemm01 geometry, stats+max/min ===
__global__ __launch_bounds__(256) void gemm2_kernel(const float* __restrict__ W,
                                                    const float* __restrict__ bias) {
    constexpr int KIN = 64, OUTF = 128, COLS = 64, RPB = 128, XS = RPB + 4;

    extern __shared__ float sm[];
    float* s_x = sm;                 // [64][132]
    float* s_w = sm + KIN * XS;      // [64][64]  (this CTA's col half)
    double* sums = g_sums + 256;

    const int tid = threadIdx.x;
    const int cg = tid >> 5, rg = tid & 31;
    const int ch = blockIdx.y;
    const int col0 = ch * COLS;
    const size_t row0 = (size_t)blockIdx.x * RPB;

    for (int i = tid; i < KIN * COLS; i += 256) {
        int k = i / COLS, c = i - k * COLS;
        s_w[k * COLS + c] = W[(col0 + c) * KIN + k];
    }
    for (int i = tid; i < RPB * KIN; i += 256) {
        int r = i / KIN, k = i - r * KIN;
        float v = g_y1[(row0 + r) * KIN + k];
        v = fmaxf(fmaf(v, __ldg(&g_scale[64 + k]), __ldg(&g_shift[64 + k])), 0.f);
        s_x[k * XS + r] = v;
    }
    __syncthreads();

    unsigned long long acc[4][4];
#pragma unroll
    for (int i = 0; i < 4; i++)
#pragma unroll
        for (int j = 0; j < 4; j++) acc[i][j] = 0ull;

    const unsigned long long* s_w2 = (const unsigned long long*)s_w;
#pragma unroll 4
    for (int k = 0; k < KIN; k++) {
        float4 xq = *(const float4*)(s_x + k * XS + 4 * rg);
        unsigned long long a0 = pk_dup(xq.x), a1 = pk_dup(xq.y),
                           a2 = pk_dup(xq.z), a3 = pk_dup(xq.w);
        ulonglong2 b01 = *(const ulonglong2*)(s_w2 + ((k * COLS + cg * 8) >> 1));
        ulonglong2 b23 = *(const ulonglong2*)(s_w2 + ((k * COLS + cg * 8) >> 1) + 2);
        fma2(acc[0][0], a0, b01.x); fma2(acc[0][1], a0, b01.y);
        fma2(acc[0][2], a0, b23.x); fma2(acc[0][3], a0, b23.y);
        fma2(acc[1][0], a1, b01.x); fma2(acc[1][1], a1, b01.y);
        fma2(acc[1][2], a1, b23.x); fma2(acc[1][3], a1, b23.y);
        fma2(acc[2][0], a2, b01.x); fma2(acc[2][1], a2, b01.y);
        fma2(acc[2][2], a2, b23.x); fma2(acc[2][3], a2, b23.y);
        fma2(acc[3][0], a3, b01.x); fma2(acc[3][1], a3, b01.y);
        fma2(acc[3][2], a3, b23.x); fma2(acc[3][3], a3, b23.y);
    }

    float bl[8];
#pragma unroll
    for (int j = 0; j < 8; j++) bl[j] = bias[col0 + cg * 8 + j];
    float psum[8], psq[8], tmax[8], tmin[8];
#pragma unroll
    for (int j = 0; j < 8; j++) {
        psum[j] = 0.f; psq[j] = 0.f; tmax[j] = -1e30f; tmin[j] = 1e30f;
    }

#pragma unroll
    for (int r = 0; r < 4; r++) {
        float yv[8];
#pragma unroll
        for (int jp = 0; jp < 4; jp++) unpk(acc[r][jp], yv[2*jp], yv[2*jp+1]);
#pragma unroll
        for (int j = 0; j < 8; j++) {
            yv[j] = yv[j] + bl[j];
            psum[j] += yv[j];
            psq[j]  = fmaf(yv[j], yv[j], psq[j]);
            tmax[j] = fmaxf(tmax[j], yv[j]);
            tmin[j] = fminf(tmin[j], yv[j]);
        }
    }
#pragma unroll
    for (int j = 0; j < 8; j++) {
#pragma unroll
        for (int off = 16; off; off >>= 1) {
            psum[j] += __shfl_down_sync(0xffffffffu, psum[j], off);
            psq[j]  += __shfl_down_sync(0xffffffffu, psq[j],  off);
        }
    }
    if ((tid & 31) == 0) {
        int gc = col0 + cg * 8;
#pragma unroll
        for (int j = 0; j < 8; j++) {
            atomicAdd(&sums[gc + j],        (double)psum[j]);
            atomicAdd(&sums[OUTF + gc + j], (double)psq[j]);
        }
    }
#pragma unroll
    for (int j = 0; j < 8; j++) {
#pragma unroll
        for (int off = 4; off; off >>= 1) {
            tmax[j] = fmaxf(tmax[j], __shfl_down_sync(0xffffffffu, tmax[j], off, 8));
            tmin[j] = fminf(tmin[j], __shfl_down_sync(0xffffffffu, tmin[j], off, 8));
        }
    }
    if ((rg & 7) == 0) {
        size_t samp = row0 / 32 + (rg >> 3);
        int gc = col0 + cg * 8;
        float* pma = &g_ymax[samp * 128 + gc];
        float* pmi = &g_ymin[samp * 128 + gc];
        ((float4*)pma)[0] = make_float4(tmax[0], tmax[1], tmax[2], tmax[3]);
        ((float4*)pma)[1] = make_float4(tmax[4], tmax[5], tmax[6], tmax[7]);
        ((float4*)pmi)[0] = make_float4(tmin[0], tmin[1], tmin[2], tmin[3]);
        ((float4*)pmi)[1] = make_float4(tmin[4], tmin[5], tmin[6], tmin[7]);
    }
}

__global__ void finalize_kernel(const float* __restrict__ g, const float* __restrict__ be,
                                int O, int soff, int scoff) {
    int c = threadIdx.x;
    if (c >= O) return;
    double n = (double)NROWS;
    double mean = g_sums[soff + c] / n;
    double var  = g_sums[soff + O + c] / n - mean * mean;
    double sc   = (double)g[c] * rsqrt(var + 1e-5);
    g_scale[scoff + c] = (float)sc;
    g_shift[scoff + c] = (float)((double)be[c] - mean * sc);
}

__global__ __launch_bounds__(128) void maxpool_kernel(float* __restrict__ out) {
    int bs = blockIdx.x, c = threadIdx.x;
    float sc = g_scale[128 + c], sh = g_shift[128 + c];
    float v = (sc >= 0.f) ? g_ymax[(size_t)bs * 128 + c] : g_ymin[(size_t)bs * 128 + c];
    out[OUT_OFF + (size_t)bs * 128 + c] = fmaxf(fmaf(v, sc, sh), 0.f);
}

// ============================ launcher ====================================
extern "C" void kernel_launch(void* const* d_in, const int* in_sizes, int n_in,
                              void* d_out, int out_size) {
    const float* data = (const float*)d_in[0];
    const float* feat = (const float*)d_in[1];
    const int*   initf = (const int*)d_in[2];
    const float* W0 = (const float*)d_in[3];  const float* b0 = (const float*)d_in[4];
    const float* g0 = (const float*)d_in[5];  const float* be0 = (const float*)d_in[6];
    const float* W1 = (const float*)d_in[7];  const float* b1 = (const float*)d_in[8];
    const float* g1 = (const float*)d_in[9];  const float* be1 = (const float*)d_in[10];
    const float* W2 = (const float*)d_in[11]; const float* b2 = (const float*)d_in[12];
    const float* g2 = (const float*)d_in[13]; const float* be2 = (const float*)d_in[14];
    float* out = (float*)d_out;

    const int smf = NPTS * 3 * 4 + 128 * 4;          // fps: 49664
    const int smb = 33824;                           // build
    const int sm0 = (68*132 + 68*64) * 4;            // 53312
    const int sm1 = (64*132 + 64*64) * 4;            // 50176
    const int sm2 = (64*132 + 64*64) * 4;            // 50176
    cudaFuncSetAttribute((const void*)fps_kernel,       cudaFuncAttributeMaxDynamicSharedMemorySize, smf);
    cudaFuncSetAttribute((const void*)build_kernel,     cudaFuncAttributeMaxDynamicSharedMemorySize, smb);
    cudaFuncSetAttribute((const void*)gemm01_kernel<0>, cudaFuncAttributeMaxDynamicSharedMemorySize, sm0);
    cudaFuncSetAttribute((const void*)gemm01_kernel<1>, cudaFuncAttributeMaxDynamicSharedMemorySize, sm1);
    cudaFuncSetAttribute((const void*)gemm2_kernel,     cudaFuncAttributeMaxDynamicSharedMemorySize, sm2);

    zero_stats_kernel<<<1, 512>>>();
    fps_kernel<<<NBATCH, 1024, smf>>>(data, initf, out);
    probe_kernel<<<1, 32>>>();   // keeps ncu capture window on build_kernel
    build_kernel<<<NBATCH * NSAMP, 512, smb>>>(data, feat);
    gemm01_kernel<0><<<NROWS / 128, 256, sm0>>>(W0, b0);
    finalize_kernel<<<1, 128>>>(g0, be0, 64, 0, 0);
    gemm01_kernel<1><<<NROWS / 128, 256, sm1>>>(W1, b1);
    finalize_kernel<<<1, 128>>>(g1, be1, 64, 128, 64);
    gemm2_kernel<<<dim3(NROWS / 128, 2), 256, sm2>>>(W2, b2);
    finalize_kernel<<<1, 128>>>(g2, be2, 128, 256, 128);
    maxpool_kernel<<<NBATCH * NSAMP, 128>>>(out);
}

// round 15
// speedup vs baseline: 1.1355x; 1.1355x over previous
#include <cuda_runtime.h>
#include <math.h>

#define NPTS   4096
#define NBATCH 16
#define NSAMP  1024
#define NK     32
#define NROWS  (NBATCH*NSAMP*NK)      /* 524288 */
#define NSAMPT (NBATCH*NSAMP)         /* 16384  */
#define OUT_OFF (NBATCH*NSAMP*3)      /* 49152  */

// ---------------- device scratch (no allocations allowed) ----------------
__device__ float  g_centroids[NBATCH*NSAMP*3];
__device__ float  g_x0[(size_t)NROWS*68];
__device__ float  g_y0[(size_t)NROWS*64];
__device__ float  g_y1[(size_t)NROWS*64];
__device__ float  g_ymax[(size_t)NSAMPT*128];
__device__ float  g_ymin[(size_t)NSAMPT*128];
__device__ double g_sums[512];
__device__ float  g_scale[256];
__device__ float  g_shift[256];

__global__ void zero_stats_kernel() {
    int t = threadIdx.x;
    if (t < 512) g_sums[t] = 0.0;
}

// no-ops: position the fixed-slot ncu capture onto fps_kernel this round
__global__ void probe_kernel() {}
__global__ void probe2_kernel() {}

// ---------------- packed f32x2 helpers (exact RN f32 math) ---------------
__device__ __forceinline__ unsigned long long pk_dup(float x) {
    unsigned long long r; unsigned u = __float_as_uint(x);
    asm("mov.b64 %0, {%1, %1};" : "=l"(r) : "r"(u));
    return r;
}
__device__ __forceinline__ void fma2(unsigned long long& d, unsigned long long a,
                                     unsigned long long b) {
    asm("fma.rn.f32x2 %0, %1, %2, %0;" : "+l"(d) : "l"(a), "l"(b));
}
__device__ __forceinline__ void unpk(unsigned long long v, float& lo, float& hi) {
    unsigned a, b;
    asm("mov.b64 {%0, %1}, %2;" : "=r"(a), "=r"(b) : "l"(v));
    lo = __uint_as_float(a); hi = __uint_as_float(b);
}

// ============================ FPS (REDUX version, banked win) ==============
__global__ __launch_bounds__(1024) void fps_kernel(const float* __restrict__ data,
                                                   const int* __restrict__ initf,
                                                   float* __restrict__ out) {
    extern __shared__ float fsm[];
    float* s_px = fsm;
    float* s_py = fsm + NPTS;
    float* s_pz = fsm + 2*NPTS;
    unsigned* s_rd = (unsigned*)(fsm + 3*NPTS);   // 64 (double-buffered)
    unsigned* s_ri = s_rd + 64;

    const int b = blockIdx.x, tid = threadIdx.x;
    const int lane = tid & 31, wid = tid >> 5;
    const float* db = data + (size_t)b * NPTS * 3;

    float px[4], py[4], pz[4], dist[4];
#pragma unroll
    for (int i = 0; i < 4; i++) {
        int n = tid + i * 1024;
        float x = db[n*3+0], y = db[n*3+1], z = db[n*3+2];
        px[i] = x; py[i] = y; pz[i] = z;
        s_px[n] = x; s_py[n] = y; s_pz[n] = z;
        dist[i] = 1e10f;
    }
    int far = __ldg(initf + b);
    __syncthreads();

    for (int s = 0; s < NSAMP; s++) {
        float cx = s_px[far], cy = s_py[far], cz = s_pz[far];
        if (tid == 0) {
            int o = (b*NSAMP + s) * 3;
            out[o] = cx; out[o+1] = cy; out[o+2] = cz;
            g_centroids[o] = cx; g_centroids[o+1] = cy; g_centroids[o+2] = cz;
        }
        unsigned long long best = 0ull;
#pragma unroll
        for (int i = 0; i < 4; i++) {
            float dx = px[i]-cx, dy = py[i]-cy, dz = pz[i]-cz;
            float d = dx*dx + dy*dy + dz*dz;
            dist[i] = fminf(dist[i], d);
            unsigned long long key =
                ((unsigned long long)__float_as_uint(dist[i]) << 32) |
                (unsigned)(4095 - (tid + i*1024));
            best = best > key ? best : key;
        }
        unsigned d32 = (unsigned)(best >> 32);
        unsigned i32 = (unsigned)best;
        unsigned wd = __reduce_max_sync(0xffffffffu, d32);
        unsigned ci = (d32 == wd) ? i32 : 0u;
        unsigned wi = __reduce_max_sync(0xffffffffu, ci);
        int par = (s & 1) * 32;
        if (lane == 0) { s_rd[par + wid] = wd; s_ri[par + wid] = wi; }
        __syncthreads();
        unsigned dv = s_rd[par + lane], iv = s_ri[par + lane];
        unsigned gd = __reduce_max_sync(0xffffffffu, dv);
        unsigned c2 = (dv == gd) ? iv : 0u;
        unsigned gi = __reduce_max_sync(0xffffffffu, c2);
        far = 4095 - (int)gi;
    }
}

// ==================== stage 2+3: top64 -> top32 -> x0 rows ================
struct Stage3 {
    float px[64], py[64], pz[64];
    unsigned long long sk[64];
    float snx[32], sny[32], snz[32], zw[32];
    int   tk[32];
};

__device__ __forceinline__ unsigned ord_f32(float v) {
    unsigned u = __float_as_uint(v);
    return (u & 0x80000000u) ? ~u : (u | 0x80000000u);
}

// Bit-exact replication of the reference square-dist (verified passing):
__device__ __forceinline__ float sqdist_ref(float cx, float cy, float cz, float an2,
                                            float x, float y, float z) {
    float e   = __fmaf_rn(cz, z, __fmaf_rn(cy, y, __fmul_rn(cx, x)));
    float bn2 = __fadd_rn(__fadd_rn(__fmul_rn(x, x), __fmul_rn(y, y)), __fmul_rn(z, z));
    return __fadd_rn(__fadd_rn(__fmul_rn(-2.f, e), an2), bn2);
}

// Round-13 build (411us measured): 512 threads, 33.8KB smem, 2048 bins,
// full-CTA bitonic sorts (the warp-0-only variant serialized and regressed).
__global__ __launch_bounds__(512) void build_kernel(const float* __restrict__ data,
                                                    const float* __restrict__ feat) {
    extern __shared__ char bsm[];
    unsigned*           s_u    = (unsigned*)bsm;                      // 4096*4 = 16384
    unsigned int*       s_hist = (unsigned int*)(bsm + 16384);        // 2048*4 = 8192
    unsigned long long* s_cand = (unsigned long long*)(bsm + 24576);  // 1024*8 = 8192
    int*                s_tot  = (int*)(bsm + 32768);                 // 256*4  = 1024
    int*                s_ctl  = (int*)(bsm + 33792);                 // [0]=T [1]=m

    const int tid = threadIdx.x;
    const int b = blockIdx.x >> 10, s = blockIdx.x & 1023;
    const float* db = data + (size_t)b * NPTS * 3;
    const int co = (b*NSAMP + s) * 3;
    const float cx = g_centroids[co], cy = g_centroids[co+1], cz = g_centroids[co+2];
    const float an2 = __fadd_rn(__fadd_rn(__fmul_rn(cx, cx), __fmul_rn(cy, cy)),
                                __fmul_rn(cz, cz));

    {
        uint4* hz = (uint4*)s_hist;
        for (int i = tid; i < 512; i += 512) hz[i] = make_uint4(0u, 0u, 0u, 0u);
    }
    if (tid == 0) s_ctl[1] = 0;
    __syncthreads();

    // pass 1: compute 32-bit ordered keys once, cache, histogram top 11 bits
    for (int i = 0; i < 8; i++) {
        int n = tid + i * 512;
        float x = db[n*3], y = db[n*3+1], z = db[n*3+2];
        float v = sqdist_ref(cx, cy, cz, an2, x, y, z);
        unsigned u = ord_f32(v);
        s_u[n] = u;
        atomicAdd(&s_hist[u >> 21], 1u);
    }
    __syncthreads();

    // chunk totals (8 bins per thread, 256 chunks), then single-warp suffix scan
    if (tid < 256) {
        unsigned tot = 0;
        for (int j = 0; j < 8; j++) tot += s_hist[tid*8 + j];
        s_tot[tid] = (int)tot;
    }
    __syncthreads();
    if (tid < 32) {
        int base = tid * 8;
        int t[8]; int S = 0;
#pragma unroll
        for (int j = 0; j < 8; j++) { t[j] = s_tot[base + j]; S += t[j]; }
        int suf = S;   // inclusive suffix over lanes
#pragma unroll
        for (int off = 1; off < 32; off <<= 1) {
            int v = __shfl_down_sync(0xffffffffu, suf, off);
            if (tid + off < 32) suf += v;
        }
        int run = suf - S;   // sum of chunks above this lane's range
#pragma unroll
        for (int j = 7; j >= 0; j--) {
            s_tot[base + j] = run;   // cum[c] = totals of chunks > c
            run += t[j];
        }
    }
    __syncthreads();
    if (tid < 256) {
        unsigned cum = (unsigned)s_tot[tid];
        for (int j = 7; j >= 0; j--) {
            unsigned h = s_hist[tid*8 + j];
            if (cum < 64u && cum + h >= 64u) s_ctl[0] = tid*8 + j;   // unique crossing
            cum += h;
        }
    }
    __syncthreads();
    const unsigned T = (unsigned)s_ctl[0];

    // pass 2: pure smem scan of cached keys, push candidates with bin >= T
    for (int i = 0; i < 8; i++) {
        int n = tid + i * 512;
        unsigned u = s_u[n];
        if ((u >> 21) >= T) {
            int slot = atomicAdd(&s_ctl[1], 1);
            if (slot < 1024)
                s_cand[slot] = ((unsigned long long)u << 32) | (unsigned)(4095 - n);
        }
    }
    __syncthreads();
    int M = s_ctl[1]; if (M > 1024) M = 1024;
    int P = 64; while (P < M) P <<= 1;
    for (int i = M + tid; i < P; i += 512) s_cand[i] = 0ull;

    // bitonic sort descending (full-CTA — measured best)
    for (int k = 2; k <= P; k <<= 1)
        for (int j = k >> 1; j > 0; j >>= 1) {
            __syncthreads();
            for (int i = tid; i < P; i += 512) {
                int ix = i ^ j;
                if (ix > i) {
                    unsigned long long a = s_cand[i], c = s_cand[ix];
                    if (((i & k) == 0) ? (a < c) : (a > c)) { s_cand[i] = c; s_cand[ix] = a; }
                }
            }
        }
    __syncthreads();

    Stage3* st = (Stage3*)s_hist;   // alias dead histogram (8KB >= 1.9KB)
    if (tid < 64) {
        int id = 4095 - (int)(unsigned)(s_cand[tid] & 0xFFFFFFFFull);
        st->px[tid] = db[id*3]; st->py[tid] = db[id*3+1]; st->pz[tid] = db[id*3+2];
    }
    __syncthreads();
    if (tid < 64) {
        float sc = fabsf(st->pz[tid] - st->pz[(tid + 63) & 63]);   // roll(+1)
        st->sk[tid] = ((unsigned long long)__float_as_uint(sc) << 32) | (unsigned)(63 - tid);
    }
    for (int k = 2; k <= 64; k <<= 1)
        for (int j = k >> 1; j > 0; j >>= 1) {
            __syncthreads();
            if (tid < 64) {
                int i = tid, ix = i ^ j;
                if (ix > i) {
                    unsigned long long a = st->sk[i], c = st->sk[ix];
                    if (((i & k) == 0) ? (a < c) : (a > c)) { st->sk[i] = c; st->sk[ix] = a; }
                }
            }
        }
    __syncthreads();

    if (tid < 32) {
        int j = 63 - (int)(unsigned)(st->sk[tid] & 63ull);   // tki
        float sx = st->px[j] - cx, sy = st->py[j] - cy, sz = st->pz[j] - cz;
        float w = fabsf(st->pz[j] - cz);
        float m = w;
#pragma unroll
        for (int off = 16; off; off >>= 1) m = fmaxf(m, __shfl_xor_sync(0xffffffffu, m, off));
        float e = expf(w - m);
        float su = e;
#pragma unroll
        for (int off = 16; off; off >>= 1) su += __shfl_xor_sync(0xffffffffu, su, off);
        st->snx[tid] = sx; st->sny[tid] = sy; st->snz[tid] = sz;
        st->zw[tid] = e / su;
        st->tk[tid] = j;
    }
    __syncthreads();

    size_t R0 = (size_t)(b*NSAMP + s) * NK;
    for (int e = tid; e < NK * 68; e += 512) {
        int k = e / 68, c = e - k * 68;
        float val;
        if (c < 3)        val = (c == 0 ? st->snx[k] : (c == 1 ? st->sny[k] : st->snz[k])) * st->zw[k];
        else if (c < 67)  val = feat[((size_t)b*NPTS + st->tk[k]) * 64 + (c - 3)] * st->zw[k];
        else              val = 0.f;
        g_x0[(R0 + k) * 68 + c] = val;
    }
}

// ==================== GEMM layers 0/1 (round-5 verbatim, 219us) ===========
template<int LAYER>
__global__ __launch_bounds__(256) void gemm01_kernel(const float* __restrict__ W,
                                                     const float* __restrict__ bias) {
    constexpr int KIN   = (LAYER == 0) ? 68 : 64;
    constexpr int KREAL = (LAYER == 0) ? 67 : 64;
    constexpr int OUT   = 64;
    constexpr int RPB   = 128;
    constexpr int XS    = RPB + 4;

    extern __shared__ float sm[];
    float* s_x = sm;                 // [KIN][XS]
    float* s_w = sm + KIN * XS;      // [KIN][OUT]

    const float* X = (LAYER == 0) ? g_x0 : g_y0;
    float*       Y = (LAYER == 0) ? g_y0 : g_y1;
    double* sums = g_sums + ((LAYER == 0) ? 0 : 128);

    const int tid = threadIdx.x;
    const int cg = tid >> 5, rg = tid & 31;
    const size_t row0 = (size_t)blockIdx.x * RPB;

    for (int i = tid; i < KIN * OUT; i += 256) {
        int k = i / OUT, c = i - k * OUT;
        s_w[k * OUT + c] = (k < KREAL) ? W[c * KREAL + k] : 0.f;
    }
    for (int i = tid; i < RPB * KIN; i += 256) {
        int r = i / KIN, k = i - r * KIN;
        float v = X[(row0 + r) * KIN + k];
        if (LAYER > 0)
            v = fmaxf(fmaf(v, __ldg(&g_scale[k]), __ldg(&g_shift[k])), 0.f);
        s_x[k * XS + r] = v;
    }
    __syncthreads();

    unsigned long long acc[4][4];
#pragma unroll
    for (int i = 0; i < 4; i++)
#pragma unroll
        for (int j = 0; j < 4; j++) acc[i][j] = 0ull;

    const unsigned long long* s_w2 = (const unsigned long long*)s_w;
#pragma unroll 4
    for (int k = 0; k < KIN; k++) {
        float4 xq = *(const float4*)(s_x + k * XS + 4 * rg);
        unsigned long long a0 = pk_dup(xq.x), a1 = pk_dup(xq.y),
                           a2 = pk_dup(xq.z), a3 = pk_dup(xq.w);
        ulonglong2 b01 = *(const ulonglong2*)(s_w2 + ((k * OUT + cg * 8) >> 1));
        ulonglong2 b23 = *(const ulonglong2*)(s_w2 + ((k * OUT + cg * 8) >> 1) + 2);
        fma2(acc[0][0], a0, b01.x); fma2(acc[0][1], a0, b01.y);
        fma2(acc[0][2], a0, b23.x); fma2(acc[0][3], a0, b23.y);
        fma2(acc[1][0], a1, b01.x); fma2(acc[1][1], a1, b01.y);
        fma2(acc[1][2], a1, b23.x); fma2(acc[1][3], a1, b23.y);
        fma2(acc[2][0], a2, b01.x); fma2(acc[2][1], a2, b01.y);
        fma2(acc[2][2], a2, b23.x); fma2(acc[2][3], a2, b23.y);
        fma2(acc[3][0], a3, b01.x); fma2(acc[3][1], a3, b01.y);
        fma2(acc[3][2], a3, b23.x); fma2(acc[3][3], a3, b23.y);
    }

    float bl[8];
#pragma unroll
    for (int j = 0; j < 8; j++) bl[j] = bias[cg * 8 + j];
    float psum[8], psq[8];
#pragma unroll
    for (int j = 0; j < 8; j++) { psum[j] = 0.f; psq[j] = 0.f; }

#pragma unroll
    for (int r = 0; r < 4; r++) {
        float yv[8];
#pragma unroll
        for (int jp = 0; jp < 4; jp++) unpk(acc[r][jp], yv[2*jp], yv[2*jp+1]);
#pragma unroll
        for (int j = 0; j < 8; j++) {
            yv[j] = yv[j] + bl[j];
            psum[j] += yv[j];
            psq[j]  = fmaf(yv[j], yv[j], psq[j]);
        }
        size_t row = row0 + 4 * rg + r;
        float4* dst = (float4*)&Y[row * OUT + cg * 8];
        dst[0] = make_float4(yv[0], yv[1], yv[2], yv[3]);
        dst[1] = make_float4(yv[4], yv[5], yv[6], yv[7]);
    }
#pragma unroll
    for (int j = 0; j < 8; j++) {
#pragma unroll
        for (int off = 16; off; off >>= 1) {
            psum[j] += __shfl_down_sync(0xffffffffu, psum[j], off);
            psq[j]  += __shfl_down_sync(0xffffffffu, psq[j],  off);
        }
    }
    if ((tid & 31) == 0) {
#pragma unroll
        for (int j = 0; j < 8; j++) {
            atomicAdd(&sums[cg * 8 + j],       (double)psum[j]);
            atomicAdd(&sums[OUT + cg * 8 + j], (double)psq[j]);
        }
    }
}

// ==== GEMM layer 2: col-split (grid.y=2), gemm01 geometry, stats+max/min ===
__global__ __launch_bounds__(256) void gemm2_kernel(const float* __restrict__ W,
                                                    const float* __restrict__ bias) {
    constexpr int KIN = 64, OUTF = 128, COLS = 64, RPB = 128, XS = RPB + 4;

    extern __shared__ float sm[];
    float* s_x = sm;                 // [64][132]
    float* s_w = sm + KIN * XS;      // [64][64]  (this CTA's col half)
    double* sums = g_sums + 256;

    const int tid = threadIdx.x;
    const int cg = tid >> 5, rg = tid & 31;
    const int ch = blockIdx.y;
    const int col0 = ch * COLS;
    const size_t row0 = (size_t)blockIdx.x * RPB;

    for (int i = tid; i < KIN * COLS; i += 256) {
        int k = i / COLS, c = i - k * COLS;
        s_w[k * COLS + c] = W[(col0 + c) * KIN + k];
    }
    for (int i = tid; i < RPB * KIN; i += 256) {
        int r = i / KIN, k = i - r * KIN;
        float v = g_y1[(row0 + r) * KIN + k];
        v = fmaxf(fmaf(v, __ldg(&g_scale[64 + k]), __ldg(&g_shift[64 + k])), 0.f);
        s_x[k * XS + r] = v;
    }
    __syncthreads();

    unsigned long long acc[4][4];
#pragma unroll
    for (int i = 0; i < 4; i++)
#pragma unroll
        for (int j = 0; j < 4; j++) acc[i][j] = 0ull;

    const unsigned long long* s_w2 = (const unsigned long long*)s_w;
#pragma unroll 4
    for (int k = 0; k < KIN; k++) {
        float4 xq = *(const float4*)(s_x + k * XS + 4 * rg);
        unsigned long long a0 = pk_dup(xq.x), a1 = pk_dup(xq.y),
                           a2 = pk_dup(xq.z), a3 = pk_dup(xq.w);
        ulonglong2 b01 = *(const ulonglong2*)(s_w2 + ((k * COLS + cg * 8) >> 1));
        ulonglong2 b23 = *(const ulonglong2*)(s_w2 + ((k * COLS + cg * 8) >> 1) + 2);
        fma2(acc[0][0], a0, b01.x); fma2(acc[0][1], a0, b01.y);
        fma2(acc[0][2], a0, b23.x); fma2(acc[0][3], a0, b23.y);
        fma2(acc[1][0], a1, b01.x); fma2(acc[1][1], a1, b01.y);
        fma2(acc[1][2], a1, b23.x); fma2(acc[1][3], a1, b23.y);
        fma2(acc[2][0], a2, b01.x); fma2(acc[2][1], a2, b01.y);
        fma2(acc[2][2], a2, b23.x); fma2(acc[2][3], a2, b23.y);
        fma2(acc[3][0], a3, b01.x); fma2(acc[3][1], a3, b01.y);
        fma2(acc[3][2], a3, b23.x); fma2(acc[3][3], a3, b23.y);
    }

    float bl[8];
#pragma unroll
    for (int j = 0; j < 8; j++) bl[j] = bias[col0 + cg * 8 + j];
    float psum[8], psq[8], tmax[8], tmin[8];
#pragma unroll
    for (int j = 0; j < 8; j++) {
        psum[j] = 0.f; psq[j] = 0.f; tmax[j] = -1e30f; tmin[j] = 1e30f;
    }

#pragma unroll
    for (int r = 0; r < 4; r++) {
        float yv[8];
#pragma unroll
        for (int jp = 0; jp < 4; jp++) unpk(acc[r][jp], yv[2*jp], yv[2*jp+1]);
#pragma unroll
        for (int j = 0; j < 8; j++) {
            yv[j] = yv[j] + bl[j];
            psum[j] += yv[j];
            psq[j]  = fmaf(yv[j], yv[j], psq[j]);
            tmax[j] = fmaxf(tmax[j], yv[j]);
            tmin[j] = fminf(tmin[j], yv[j]);
        }
    }
#pragma unroll
    for (int j = 0; j < 8; j++) {
#pragma unroll
        for (int off = 16; off; off >>= 1) {
            psum[j] += __shfl_down_sync(0xffffffffu, psum[j], off);
            psq[j]  += __shfl_down_sync(0xffffffffu, psq[j],  off);
        }
    }
    if ((tid & 31) == 0) {
        int gc = col0 + cg * 8;
#pragma unroll
        for (int j = 0; j < 8; j++) {
            atomicAdd(&sums[gc + j],        (double)psum[j]);
            atomicAdd(&sums[OUTF + gc + j], (double)psq[j]);
        }
    }
#pragma unroll
    for (int j = 0; j < 8; j++) {
#pragma unroll
        for (int off = 4; off; off >>= 1) {
            tmax[j] = fmaxf(tmax[j], __shfl_down_sync(0xffffffffu, tmax[j], off, 8));
            tmin[j] = fminf(tmin[j], __shfl_down_sync(0xffffffffu, tmin[j], off, 8));
        }
    }
    if ((rg & 7) == 0) {
        size_t samp = row0 / 32 + (rg >> 3);
        int gc = col0 + cg * 8;
        float* pma = &g_ymax[samp * 128 + gc];
        float* pmi = &g_ymin[samp * 128 + gc];
        ((float4*)pma)[0] = make_float4(tmax[0], tmax[1], tmax[2], tmax[3]);
        ((float4*)pma)[1] = make_float4(tmax[4], tmax[5], tmax[6], tmax[7]);
        ((float4*)pmi)[0] = make_float4(tmin[0], tmin[1], tmin[2], tmin[3]);
        ((float4*)pmi)[1] = make_float4(tmin[4], tmin[5], tmin[6], tmin[7]);
    }
}

__global__ void finalize_kernel(const float* __restrict__ g, const float* __restrict__ be,
                                int O, int soff, int scoff) {
    int c = threadIdx.x;
    if (c >= O) return;
    double n = (double)NROWS;
    double mean = g_sums[soff + c] / n;
    double var  = g_sums[soff + O + c] / n - mean * mean;
    double sc   = (double)g[c] * rsqrt(var + 1e-5);
    g_scale[scoff + c] = (float)sc;
    g_shift[scoff + c] = (float)((double)be[c] - mean * sc);
}

__global__ __launch_bounds__(128) void maxpool_kernel(float* __restrict__ out) {
    int bs = blockIdx.x, c = threadIdx.x;
    float sc = g_scale[128 + c], sh = g_shift[128 + c];
    float v = (sc >= 0.f) ? g_ymax[(size_t)bs * 128 + c] : g_ymin[(size_t)bs * 128 + c];
    out[OUT_OFF + (size_t)bs * 128 + c] = fmaxf(fmaf(v, sc, sh), 0.f);
}

// ============================ launcher ====================================
extern "C" void kernel_launch(void* const* d_in, const int* in_sizes, int n_in,
                              void* d_out, int out_size) {
    const float* data = (const float*)d_in[0];
    const float* feat = (const float*)d_in[1];
    const int*   initf = (const int*)d_in[2];
    const float* W0 = (const float*)d_in[3];  const float* b0 = (const float*)d_in[4];
    const float* g0 = (const float*)d_in[5];  const float* be0 = (const float*)d_in[6];
    const float* W1 = (const float*)d_in[7];  const float* b1 = (const float*)d_in[8];
    const float* g1 = (const float*)d_in[9];  const float* be1 = (const float*)d_in[10];
    const float* W2 = (const float*)d_in[11]; const float* b2 = (const float*)d_in[12];
    const float* g2 = (const float*)d_in[13]; const float* be2 = (const float*)d_in[14];
    float* out = (float*)d_out;

    const int smf = NPTS * 3 * 4 + 128 * 4;          // fps: 49664
    const int smb = 33824;                           // build
    const int sm0 = (68*132 + 68*64) * 4;            // 53312
    const int sm1 = (64*132 + 64*64) * 4;            // 50176
    const int sm2 = (64*132 + 64*64) * 4;            // 50176
    cudaFuncSetAttribute((const void*)fps_kernel,       cudaFuncAttributeMaxDynamicSharedMemorySize, smf);
    cudaFuncSetAttribute((const void*)build_kernel,     cudaFuncAttributeMaxDynamicSharedMemorySize, smb);
    cudaFuncSetAttribute((const void*)gemm01_kernel<0>, cudaFuncAttributeMaxDynamicSharedMemorySize, sm0);
    cudaFuncSetAttribute((const void*)gemm01_kernel<1>, cudaFuncAttributeMaxDynamicSharedMemorySize, sm1);
    cudaFuncSetAttribute((const void*)gemm2_kernel,     cudaFuncAttributeMaxDynamicSharedMemorySize, sm2);

    zero_stats_kernel<<<1, 512>>>();
    probe_kernel<<<1, 32>>>();
    probe2_kernel<<<1, 32>>>();   // fps is now the 4th launch -> ncu captures it
    fps_kernel<<<NBATCH, 1024, smf>>>(data, initf, out);
    build_kernel<<<NBATCH * NSAMP, 512, smb>>>(data, feat);
    gemm01_kernel<0><<<NROWS / 128, 256, sm0>>>(W0, b0);
    finalize_kernel<<<1, 128>>>(g0, be0, 64, 0, 0);
    gemm01_kernel<1><<<NROWS / 128, 256, sm1>>>(W1, b1);
    finalize_kernel<<<1, 128>>>(g1, be1, 64, 128, 64);
    gemm2_kernel<<<dim3(NROWS / 128, 2), 256, sm2>>>(W2, b2);
    finalize_kernel<<<1, 128>>>(g2, be2, 128, 256, 128);
    maxpool_kernel<<<NBATCH * NSAMP, 128>>>(out);
}

// round 16
// speedup vs baseline: 1.1486x; 1.0116x over previous
#include <cuda_runtime.h>
#include <math.h>

#define NPTS   4096
#define NBATCH 16
#define NSAMP  1024
#define NK     32
#define NROWS  (NBATCH*NSAMP*NK)      /* 524288 */
#define NSAMPT (NBATCH*NSAMP)         /* 16384  */
#define OUT_OFF (NBATCH*NSAMP*3)      /* 49152  */

// ---------------- device scratch (no allocations allowed) ----------------
__device__ float  g_centroids[NBATCH*NSAMP*3];
__device__ float  g_x0[(size_t)NROWS*68];
__device__ float  g_y0[(size_t)NROWS*64];
__device__ float  g_y1[(size_t)NROWS*64];
__device__ float  g_ymax[(size_t)NSAMPT*128];
__device__ float  g_ymin[(size_t)NSAMPT*128];
__device__ double g_sums[512];
__device__ float  g_scale[256];
__device__ float  g_shift[256];

__global__ void zero_stats_kernel() {
    int t = threadIdx.x;
    if (t < 512) g_sums[t] = 0.0;
}

// no-ops: keep the fixed-slot ncu capture on fps_kernel (verify this round's fix)
__global__ void probe_kernel() {}
__global__ void probe2_kernel() {}

// ---------------- packed f32x2 helpers (exact RN f32 math) ---------------
__device__ __forceinline__ unsigned long long pk_dup(float x) {
    unsigned long long r; unsigned u = __float_as_uint(x);
    asm("mov.b64 %0, {%1, %1};" : "=l"(r) : "r"(u));
    return r;
}
__device__ __forceinline__ void fma2(unsigned long long& d, unsigned long long a,
                                     unsigned long long b) {
    asm("fma.rn.f32x2 %0, %1, %2, %0;" : "+l"(d) : "l"(a), "l"(b));
}
__device__ __forceinline__ void unpk(unsigned long long v, float& lo, float& hi) {
    unsigned a, b;
    asm("mov.b64 {%0, %1}, %2;" : "=r"(a), "=r"(b) : "l"(v));
    lo = __uint_as_float(a); hi = __uint_as_float(b);
}

// ============================ FPS ==========================================
// Distance math untouched (bit-identical dist values). Argmax extraction
// moved to float domain: dists are all >= 0, so IEEE float compare == bits
// compare; (max bits, then max 4095-idx among equal) == (max dist, min idx).
// Saves ~13 warp-instructions/iter in an issue-bound kernel.
__global__ __launch_bounds__(1024) void fps_kernel(const float* __restrict__ data,
                                                   const int* __restrict__ initf,
                                                   float* __restrict__ out) {
    extern __shared__ float fsm[];
    float* s_px = fsm;
    float* s_py = fsm + NPTS;
    float* s_pz = fsm + 2*NPTS;
    unsigned* s_rd = (unsigned*)(fsm + 3*NPTS);   // 64 (double-buffered)
    unsigned* s_ri = s_rd + 64;

    const int b = blockIdx.x, tid = threadIdx.x;
    const int lane = tid & 31, wid = tid >> 5;
    const unsigned inv0 = (unsigned)(4095 - tid);
    const float* db = data + (size_t)b * NPTS * 3;

    float px[4], py[4], pz[4], dist[4];
#pragma unroll
    for (int i = 0; i < 4; i++) {
        int n = tid + i * 1024;
        float x = db[n*3+0], y = db[n*3+1], z = db[n*3+2];
        px[i] = x; py[i] = y; pz[i] = z;
        s_px[n] = x; s_py[n] = y; s_pz[n] = z;
        dist[i] = 1e10f;
    }
    int far = __ldg(initf + b);
    __syncthreads();

    for (int s = 0; s < NSAMP; s++) {
        float cx = s_px[far], cy = s_py[far], cz = s_pz[far];
        if (tid == 0) {
            int o = (b*NSAMP + s) * 3;
            out[o] = cx; out[o+1] = cy; out[o+2] = cz;
            g_centroids[o] = cx; g_centroids[o+1] = cy; g_centroids[o+2] = cz;
        }
#pragma unroll
        for (int i = 0; i < 4; i++) {
            float dx = px[i]-cx, dy = py[i]-cy, dz = pz[i]-cz;
            float d = dx*dx + dy*dy + dz*dz;
            dist[i] = fminf(dist[i], d);
        }
        // thread-local argmax, first index on tie (i ascending == global idx asc)
        float m = fmaxf(fmaxf(dist[0], dist[1]), fmaxf(dist[2], dist[3]));
        int bi = (dist[0] == m) ? 0 : (dist[1] == m) ? 1 : (dist[2] == m) ? 2 : 3;
        unsigned bits = __float_as_uint(m);
        unsigned wd = __reduce_max_sync(0xffffffffu, bits);
        unsigned ci = (bits == wd) ? (inv0 - (unsigned)(bi << 10)) : 0u;
        unsigned wi = __reduce_max_sync(0xffffffffu, ci);
        int par = (s & 1) * 32;
        if (lane == 0) { s_rd[par + wid] = wd; s_ri[par + wid] = wi; }
        __syncthreads();
        unsigned dv = s_rd[par + lane], iv = s_ri[par + lane];
        unsigned gd = __reduce_max_sync(0xffffffffu, dv);
        unsigned c2 = (dv == gd) ? iv : 0u;
        unsigned gi = __reduce_max_sync(0xffffffffu, c2);
        far = 4095 - (int)gi;
    }
}

// ==================== stage 2+3: top64 -> top32 -> x0 rows ================
struct Stage3 {
    float px[64], py[64], pz[64];
    unsigned long long sk[64];
    float snx[32], sny[32], snz[32], zw[32];
    int   tk[32];
};

__device__ __forceinline__ unsigned ord_f32(float v) {
    unsigned u = __float_as_uint(v);
    return (u & 0x80000000u) ? ~u : (u | 0x80000000u);
}

// Bit-exact replication of the reference square-dist (verified passing):
__device__ __forceinline__ float sqdist_ref(float cx, float cy, float cz, float an2,
                                            float x, float y, float z) {
    float e   = __fmaf_rn(cz, z, __fmaf_rn(cy, y, __fmul_rn(cx, x)));
    float bn2 = __fadd_rn(__fadd_rn(__fmul_rn(x, x), __fmul_rn(y, y)), __fmul_rn(z, z));
    return __fadd_rn(__fadd_rn(__fmul_rn(-2.f, e), an2), bn2);
}

// Round-13 build (411us measured): 512 threads, 33.8KB smem, 2048 bins,
// full-CTA bitonic sorts.
__global__ __launch_bounds__(512) void build_kernel(const float* __restrict__ data,
                                                    const float* __restrict__ feat) {
    extern __shared__ char bsm[];
    unsigned*           s_u    = (unsigned*)bsm;                      // 4096*4 = 16384
    unsigned int*       s_hist = (unsigned int*)(bsm + 16384);        // 2048*4 = 8192
    unsigned long long* s_cand = (unsigned long long*)(bsm + 24576);  // 1024*8 = 8192
    int*                s_tot  = (int*)(bsm + 32768);                 // 256*4  = 1024
    int*                s_ctl  = (int*)(bsm + 33792);                 // [0]=T [1]=m

    const int tid = threadIdx.x;
    const int b = blockIdx.x >> 10, s = blockIdx.x & 1023;
    const float* db = data + (size_t)b * NPTS * 3;
    const int co = (b*NSAMP + s) * 3;
    const float cx = g_centroids[co], cy = g_centroids[co+1], cz = g_centroids[co+2];
    const float an2 = __fadd_rn(__fadd_rn(__fmul_rn(cx, cx), __fmul_rn(cy, cy)),
                                __fmul_rn(cz, cz));

    {
        uint4* hz = (uint4*)s_hist;
        for (int i = tid; i < 512; i += 512) hz[i] = make_uint4(0u, 0u, 0u, 0u);
    }
    if (tid == 0) s_ctl[1] = 0;
    __syncthreads();

    // pass 1: compute 32-bit ordered keys once, cache, histogram top 11 bits
    for (int i = 0; i < 8; i++) {
        int n = tid + i * 512;
        float x = db[n*3], y = db[n*3+1], z = db[n*3+2];
        float v = sqdist_ref(cx, cy, cz, an2, x, y, z);
        unsigned u = ord_f32(v);
        s_u[n] = u;
        atomicAdd(&s_hist[u >> 21], 1u);
    }
    __syncthreads();

    // chunk totals (8 bins per thread, 256 chunks), then single-warp suffix scan
    if (tid < 256) {
        unsigned tot = 0;
        for (int j = 0; j < 8; j++) tot += s_hist[tid*8 + j];
        s_tot[tid] = (int)tot;
    }
    __syncthreads();
    if (tid < 32) {
        int base = tid * 8;
        int t[8]; int S = 0;
#pragma unroll
        for (int j = 0; j < 8; j++) { t[j] = s_tot[base + j]; S += t[j]; }
        int suf = S;   // inclusive suffix over lanes
#pragma unroll
        for (int off = 1; off < 32; off <<= 1) {
            int v = __shfl_down_sync(0xffffffffu, suf, off);
            if (tid + off < 32) suf += v;
        }
        int run = suf - S;   // sum of chunks above this lane's range
#pragma unroll
        for (int j = 7; j >= 0; j--) {
            s_tot[base + j] = run;   // cum[c] = totals of chunks > c
            run += t[j];
        }
    }
    __syncthreads();
    if (tid < 256) {
        unsigned cum = (unsigned)s_tot[tid];
        for (int j = 7; j >= 0; j--) {
            unsigned h = s_hist[tid*8 + j];
            if (cum < 64u && cum + h >= 64u) s_ctl[0] = tid*8 + j;   // unique crossing
            cum += h;
        }
    }
    __syncthreads();
    const unsigned T = (unsigned)s_ctl[0];

    // pass 2: pure smem scan of cached keys, push candidates with bin >= T
    for (int i = 0; i < 8; i++) {
        int n = tid + i * 512;
        unsigned u = s_u[n];
        if ((u >> 21) >= T) {
            int slot = atomicAdd(&s_ctl[1], 1);
            if (slot < 1024)
                s_cand[slot] = ((unsigned long long)u << 32) | (unsigned)(4095 - n);
        }
    }
    __syncthreads();
    int M = s_ctl[1]; if (M > 1024) M = 1024;
    int P = 64; while (P < M) P <<= 1;
    for (int i = M + tid; i < P; i += 512) s_cand[i] = 0ull;

    // bitonic sort descending (full-CTA — measured best)
    for (int k = 2; k <= P; k <<= 1)
        for (int j = k >> 1; j > 0; j >>= 1) {
            __syncthreads();
            for (int i = tid; i < P; i += 512) {
                int ix = i ^ j;
                if (ix > i) {
                    unsigned long long a = s_cand[i], c = s_cand[ix];
                    if (((i & k) == 0) ? (a < c) : (a > c)) { s_cand[i] = c; s_cand[ix] = a; }
                }
            }
        }
    __syncthreads();

    Stage3* st = (Stage3*)s_hist;   // alias dead histogram (8KB >= 1.9KB)
    if (tid < 64) {
        int id = 4095 - (int)(unsigned)(s_cand[tid] & 0xFFFFFFFFull);
        st->px[tid] = db[id*3]; st->py[tid] = db[id*3+1]; st->pz[tid] = db[id*3+2];
    }
    __syncthreads();
    if (tid < 64) {
        float sc = fabsf(st->pz[tid] - st->pz[(tid + 63) & 63]);   // roll(+1)
        st->sk[tid] = ((unsigned long long)__float_as_uint(sc) << 32) | (unsigned)(63 - tid);
    }
    for (int k = 2; k <= 64; k <<= 1)
        for (int j = k >> 1; j > 0; j >>= 1) {
            __syncthreads();
            if (tid < 64) {
                int i = tid, ix = i ^ j;
                if (ix > i) {
                    unsigned long long a = st->sk[i], c = st->sk[ix];
                    if (((i & k) == 0) ? (a < c) : (a > c)) { st->sk[i] = c; st->sk[ix] = a; }
                }
            }
        }
    __syncthreads();

    if (tid < 32) {
        int j = 63 - (int)(unsigned)(st->sk[tid] & 63ull);   // tki
        float sx = st->px[j] - cx, sy = st->py[j] - cy, sz = st->pz[j] - cz;
        float w = fabsf(st->pz[j] - cz);
        float m = w;
#pragma unroll
        for (int off = 16; off; off >>= 1) m = fmaxf(m, __shfl_xor_sync(0xffffffffu, m, off));
        float e = expf(w - m);
        float su = e;
#pragma unroll
        for (int off = 16; off; off >>= 1) su += __shfl_xor_sync(0xffffffffu, su, off);
        st->snx[tid] = sx; st->sny[tid] = sy; st->snz[tid] = sz;
        st->zw[tid] = e / su;
        st->tk[tid] = j;
    }
    __syncthreads();

    size_t R0 = (size_t)(b*NSAMP + s) * NK;
    for (int e = tid; e < NK * 68; e += 512) {
        int k = e / 68, c = e - k * 68;
        float val;
        if (c < 3)        val = (c == 0 ? st->snx[k] : (c == 1 ? st->sny[k] : st->snz[k])) * st->zw[k];
        else if (c < 67)  val = feat[((size_t)b*NPTS + st->tk[k]) * 64 + (c - 3)] * st->zw[k];
        else              val = 0.f;
        g_x0[(R0 + k) * 68 + c] = val;
    }
}

// ==================== GEMM layers 0/1 (round-5 verbatim, 219us) ===========
template<int LAYER>
__global__ __launch_bounds__(256) void gemm01_kernel(const float* __restrict__ W,
                                                     const float* __restrict__ bias) {
    constexpr int KIN   = (LAYER == 0) ? 68 : 64;
    constexpr int KREAL = (LAYER == 0) ? 67 : 64;
    constexpr int OUT   = 64;
    constexpr int RPB   = 128;
    constexpr int XS    = RPB + 4;

    extern __shared__ float sm[];
    float* s_x = sm;                 // [KIN][XS]
    float* s_w = sm + KIN * XS;      // [KIN][OUT]

    const float* X = (LAYER == 0) ? g_x0 : g_y0;
    float*       Y = (LAYER == 0) ? g_y0 : g_y1;
    double* sums = g_sums + ((LAYER == 0) ? 0 : 128);

    const int tid = threadIdx.x;
    const int cg = tid >> 5, rg = tid & 31;
    const size_t row0 = (size_t)blockIdx.x * RPB;

    for (int i = tid; i < KIN * OUT; i += 256) {
        int k = i / OUT, c = i - k * OUT;
        s_w[k * OUT + c] = (k < KREAL) ? W[c * KREAL + k] : 0.f;
    }
    for (int i = tid; i < RPB * KIN; i += 256) {
        int r = i / KIN, k = i - r * KIN;
        float v = X[(row0 + r) * KIN + k];
        if (LAYER > 0)
            v = fmaxf(fmaf(v, __ldg(&g_scale[k]), __ldg(&g_shift[k])), 0.f);
        s_x[k * XS + r] = v;
    }
    __syncthreads();

    unsigned long long acc[4][4];
#pragma unroll
    for (int i = 0; i < 4; i++)
#pragma unroll
        for (int j = 0; j < 4; j++) acc[i][j] = 0ull;

    const unsigned long long* s_w2 = (const unsigned long long*)s_w;
#pragma unroll 4
    for (int k = 0; k < KIN; k++) {
        float4 xq = *(const float4*)(s_x + k * XS + 4 * rg);
        unsigned long long a0 = pk_dup(xq.x), a1 = pk_dup(xq.y),
                           a2 = pk_dup(xq.z), a3 = pk_dup(xq.w);
        ulonglong2 b01 = *(const ulonglong2*)(s_w2 + ((k * OUT + cg * 8) >> 1));
        ulonglong2 b23 = *(const ulonglong2*)(s_w2 + ((k * OUT + cg * 8) >> 1) + 2);
        fma2(acc[0][0], a0, b01.x); fma2(acc[0][1], a0, b01.y);
        fma2(acc[0][2], a0, b23.x); fma2(acc[0][3], a0, b23.y);
        fma2(acc[1][0], a1, b01.x); fma2(acc[1][1], a1, b01.y);
        fma2(acc[1][2], a1, b23.x); fma2(acc[1][3], a1, b23.y);
        fma2(acc[2][0], a2, b01.x); fma2(acc[2][1], a2, b01.y);
        fma2(acc[2][2], a2, b23.x); fma2(acc[2][3], a2, b23.y);
        fma2(acc[3][0], a3, b01.x); fma2(acc[3][1], a3, b01.y);
        fma2(acc[3][2], a3, b23.x); fma2(acc[3][3], a3, b23.y);
    }

    float bl[8];
#pragma unroll
    for (int j = 0; j < 8; j++) bl[j] = bias[cg * 8 + j];
    float psum[8], psq[8];
#pragma unroll
    for (int j = 0; j < 8; j++) { psum[j] = 0.f; psq[j] = 0.f; }

#pragma unroll
    for (int r = 0; r < 4; r++) {
        float yv[8];
#pragma unroll
        for (int jp = 0; jp < 4; jp++) unpk(acc[r][jp], yv[2*jp], yv[2*jp+1]);
#pragma unroll
        for (int j = 0; j < 8; j++) {
            yv[j] = yv[j] + bl[j];
            psum[j] += yv[j];
            psq[j]  = fmaf(yv[j], yv[j], psq[j]);
        }
        size_t row = row0 + 4 * rg + r;
        float4* dst = (float4*)&Y[row * OUT + cg * 8];
        dst[0] = make_float4(yv[0], yv[1], yv[2], yv[3]);
        dst[1] = make_float4(yv[4], yv[5], yv[6], yv[7]);
    }
#pragma unroll
    for (int j = 0; j < 8; j++) {
#pragma unroll
        for (int off = 16; off; off >>= 1) {
            psum[j] += __shfl_down_sync(0xffffffffu, psum[j], off);
            psq[j]  += __shfl_down_sync(0xffffffffu, psq[j],  off);
        }
    }
    if ((tid & 31) == 0) {
#pragma unroll
        for (int j = 0; j < 8; j++) {
            atomicAdd(&sums[cg * 8 + j],       (double)psum[j]);
            atomicAdd(&sums[OUT + cg * 8 + j], (double)psq[j]);
        }
    }
}

// ==== GEMM layer 2: col-split (grid.y=2), gemm01 geometry, stats+max/min ===
__global__ __launch_bounds__(256) void gemm2_kernel(const float* __restrict__ W,
                                                    const float* __restrict__ bias) {
    constexpr int KIN = 64, OUTF = 128, COLS = 64, RPB = 128, XS = RPB + 4;

    extern __shared__ float sm[];
    float* s_x = sm;                 // [64][132]
    float* s_w = sm + KIN * XS;      // [64][64]  (this CTA's col half)
    double* sums = g_sums + 256;

    const int tid = threadIdx.x;
    const int cg = tid >> 5, rg = tid & 31;
    const int ch = blockIdx.y;
    const int col0 = ch * COLS;
    const size_t row0 = (size_t)blockIdx.x * RPB;

    for (int i = tid; i < KIN * COLS; i += 256) {
        int k = i / COLS, c = i - k * COLS;
        s_w[k * COLS + c] = W[(col0 + c) * KIN + k];
    }
    for (int i = tid; i < RPB * KIN; i += 256) {
        int r = i / KIN, k = i - r * KIN;
        float v = g_y1[(row0 + r) * KIN + k];
        v = fmaxf(fmaf(v, __ldg(&g_scale[64 + k]), __ldg(&g_shift[64 + k])), 0.f);
        s_x[k * XS + r] = v;
    }
    __syncthreads();

    unsigned long long acc[4][4];
#pragma unroll
    for (int i = 0; i < 4; i++)
#pragma unroll
        for (int j = 0; j < 4; j++) acc[i][j] = 0ull;

    const unsigned long long* s_w2 = (const unsigned long long*)s_w;
#pragma unroll 4
    for (int k = 0; k < KIN; k++) {
        float4 xq = *(const float4*)(s_x + k * XS + 4 * rg);
        unsigned long long a0 = pk_dup(xq.x), a1 = pk_dup(xq.y),
                           a2 = pk_dup(xq.z), a3 = pk_dup(xq.w);
        ulonglong2 b01 = *(const ulonglong2*)(s_w2 + ((k * COLS + cg * 8) >> 1));
        ulonglong2 b23 = *(const ulonglong2*)(s_w2 + ((k * COLS + cg * 8) >> 1) + 2);
        fma2(acc[0][0], a0, b01.x); fma2(acc[0][1], a0, b01.y);
        fma2(acc[0][2], a0, b23.x); fma2(acc[0][3], a0, b23.y);
        fma2(acc[1][0], a1, b01.x); fma2(acc[1][1], a1, b01.y);
        fma2(acc[1][2], a1, b23.x); fma2(acc[1][3], a1, b23.y);
        fma2(acc[2][0], a2, b01.x); fma2(acc[2][1], a2, b01.y);
        fma2(acc[2][2], a2, b23.x); fma2(acc[2][3], a2, b23.y);
        fma2(acc[3][0], a3, b01.x); fma2(acc[3][1], a3, b01.y);
        fma2(acc[3][2], a3, b23.x); fma2(acc[3][3], a3, b23.y);
    }

    float bl[8];
#pragma unroll
    for (int j = 0; j < 8; j++) bl[j] = bias[col0 + cg * 8 + j];
    float psum[8], psq[8], tmax[8], tmin[8];
#pragma unroll
    for (int j = 0; j < 8; j++) {
        psum[j] = 0.f; psq[j] = 0.f; tmax[j] = -1e30f; tmin[j] = 1e30f;
    }

#pragma unroll
    for (int r = 0; r < 4; r++) {
        float yv[8];
#pragma unroll
        for (int jp = 0; jp < 4; jp++) unpk(acc[r][jp], yv[2*jp], yv[2*jp+1]);
#pragma unroll
        for (int j = 0; j < 8; j++) {
            yv[j] = yv[j] + bl[j];
            psum[j] += yv[j];
            psq[j]  = fmaf(yv[j], yv[j], psq[j]);
            tmax[j] = fmaxf(tmax[j], yv[j]);
            tmin[j] = fminf(tmin[j], yv[j]);
        }
    }
#pragma unroll
    for (int j = 0; j < 8; j++) {
#pragma unroll
        for (int off = 16; off; off >>= 1) {
            psum[j] += __shfl_down_sync(0xffffffffu, psum[j], off);
            psq[j]  += __shfl_down_sync(0xffffffffu, psq[j],  off);
        }
    }
    if ((tid & 31) == 0) {
        int gc = col0 + cg * 8;
#pragma unroll
        for (int j = 0; j < 8; j++) {
            atomicAdd(&sums[gc + j],        (double)psum[j]);
            atomicAdd(&sums[OUTF + gc + j], (double)psq[j]);
        }
    }
#pragma unroll
    for (int j = 0; j < 8; j++) {
#pragma unroll
        for (int off = 4; off; off >>= 1) {
            tmax[j] = fmaxf(tmax[j], __shfl_down_sync(0xffffffffu, tmax[j], off, 8));
            tmin[j] = fminf(tmin[j], __shfl_down_sync(0xffffffffu, tmin[j], off, 8));
        }
    }
    if ((rg & 7) == 0) {
        size_t samp = row0 / 32 + (rg >> 3);
        int gc = col0 + cg * 8;
        float* pma = &g_ymax[samp * 128 + gc];
        float* pmi = &g_ymin[samp * 128 + gc];
        ((float4*)pma)[0] = make_float4(tmax[0], tmax[1], tmax[2], tmax[3]);
        ((float4*)pma)[1] = make_float4(tmax[4], tmax[5], tmax[6], tmax[7]);
        ((float4*)pmi)[0] = make_float4(tmin[0], tmin[1], tmin[2], tmin[3]);
        ((float4*)pmi)[1] = make_float4(tmin[4], tmin[5], tmin[6], tmin[7]);
    }
}

__global__ void finalize_kernel(const float* __restrict__ g, const float* __restrict__ be,
                                int O, int soff, int scoff) {
    int c = threadIdx.x;
    if (c >= O) return;
    double n = (double)NROWS;
    double mean = g_sums[soff + c] / n;
    double var  = g_sums[soff + O + c] / n - mean * mean;
    double sc   = (double)g[c] * rsqrt(var + 1e-5);
    g_scale[scoff + c] = (float)sc;
    g_shift[scoff + c] = (float)((double)be[c] - mean * sc);
}

__global__ __launch_bounds__(128) void maxpool_kernel(float* __restrict__ out) {
    int bs = blockIdx.x, c = threadIdx.x;
    float sc = g_scale[128 + c], sh = g_shift[128 + c];
    float v = (sc >= 0.f) ? g_ymax[(size_t)bs * 128 + c] : g_ymin[(size_t)bs * 128 + c];
    out[OUT_OFF + (size_t)bs * 128 + c] = fmaxf(fmaf(v, sc, sh), 0.f);
}

// ============================ launcher ====================================
extern "C" void kernel_launch(void* const* d_in, const int* in_sizes, int n_in,
                              void* d_out, int out_size) {
    const float* data = (const float*)d_in[0];
    const float* feat = (const float*)d_in[1];
    const int*   initf = (const int*)d_in[2];
    const float* W0 = (const float*)d_in[3];  const float* b0 = (const float*)d_in[4];
    const float* g0 = (const float*)d_in[5];  const float* be0 = (const float*)d_in[6];
    const float* W1 = (const float*)d_in[7];  const float* b1 = (const float*)d_in[8];
    const float* g1 = (const float*)d_in[9];  const float* be1 = (const float*)d_in[10];
    const float* W2 = (const float*)d_in[11]; const float* b2 = (const float*)d_in[12];
    const float* g2 = (const float*)d_in[13]; const float* be2 = (const float*)d_in[14];
    float* out = (float*)d_out;

    const int smf = NPTS * 3 * 4 + 128 * 4;          // fps: 49664
    const int smb = 33824;                           // build
    const int sm0 = (68*132 + 68*64) * 4;            // 53312
    const int sm1 = (64*132 + 64*64) * 4;            // 50176
    const int sm2 = (64*132 + 64*64) * 4;            // 50176
    cudaFuncSetAttribute((const void*)fps_kernel,       cudaFuncAttributeMaxDynamicSharedMemorySize, smf);
    cudaFuncSetAttribute((const void*)build_kernel,     cudaFuncAttributeMaxDynamicSharedMemorySize, smb);
    cudaFuncSetAttribute((const void*)gemm01_kernel<0>, cudaFuncAttributeMaxDynamicSharedMemorySize, sm0);
    cudaFuncSetAttribute((const void*)gemm01_kernel<1>, cudaFuncAttributeMaxDynamicSharedMemorySize, sm1);
    cudaFuncSetAttribute((const void*)gemm2_kernel,     cudaFuncAttributeMaxDynamicSharedMemorySize, sm2);

    zero_stats_kernel<<<1, 512>>>();
    probe_kernel<<<1, 32>>>();
    probe2_kernel<<<1, 32>>>();   // fps is the 4th launch -> ncu captures it
    fps_kernel<<<NBATCH, 1024, smf>>>(data, initf, out);
    build_kernel<<<NBATCH * NSAMP, 512, smb>>>(data, feat);
    gemm01_kernel<0><<<NROWS / 128, 256, sm0>>>(W0, b0);
    finalize_kernel<<<1, 128>>>(g0, be0, 64, 0, 0);
    gemm01_kernel<1><<<NROWS / 128, 256, sm1>>>(W1, b1);
    finalize_kernel<<<1, 128>>>(g1, be1, 64, 128, 64);
    gemm2_kernel<<<dim3(NROWS / 128, 2), 256, sm2>>>(W2, b2);
    finalize_kernel<<<1, 128>>>(g2, be2, 128, 256, 128);
    maxpool_kernel<<<NBATCH * NSAMP, 128>>>(out);
}